// round 5
// baseline (speedup 1.0000x reference)
#include <cuda_runtime.h>
#include <cuda_bf16.h>
#include <cstdint>

// ---------------- problem constants ----------------
#define NODES 50000
#define RELS  3
#define EDGES 600000
#define D_IN  128
#define D_HID 256
#define D_OUT 128

#define SCAN_N (RELS * NODES)          // 150000 segments
#define SCAN_B 512
#define SCAN_BLOCKS ((SCAN_N + SCAN_B - 1) / SCAN_B)   // 293

// ---------------- scratch ----------------
__device__ float g_xr  [(size_t)NODES * D_IN];           // 25.6 MB  x rounded to tf32
__device__ float g_seg1[(size_t)RELS * NODES * D_IN];    // 76.8 MB  (means, tf32 bits)
__device__ float g_h   [(size_t)NODES * D_HID];          // 51.2 MB  (tf32 bits)
__device__ float g_Y   [(size_t)NODES * 4 * D_OUT];      // 102.4 MB: [y0|y1|y2|self]
__device__ int   g_csr [2 * SCAN_N];                     // cnt | cur
__device__ int   g_offs[SCAN_N + 1];
__device__ int   g_bsum[SCAN_B];
__device__ int   g_elist[(size_t)RELS * EDGES];          // 7.2 MB
__device__ float g_W1  [4 * D_IN * D_HID];               // 512 x 256 (tf32 bits)
__device__ float g_W2t [D_HID * 4 * D_OUT];              // 256 x 512 (tf32 bits)
__device__ float g_b1s [D_HID];
__device__ float g_b2s [D_OUT];

__device__ __forceinline__ unsigned f2tf32(float x) {
    unsigned r;
    asm("cvt.rna.tf32.f32 %0, %1;" : "=r"(r) : "f"(x));
    return r;
}

// ---------------- utility ----------------
__global__ void zero_i(int* __restrict__ p, int n) {
    int i = blockIdx.x * blockDim.x + threadIdx.x;
    if (i < n) p[i] = 0;
}

// round x -> xr (tf32 bits), vectorized
__global__ void round_x_kernel(const float4* __restrict__ x, float4* __restrict__ xr, long n4) {
    long stride = (long)gridDim.x * blockDim.x;
    for (long i = (long)blockIdx.x * blockDim.x + threadIdx.x; i < n4; i += stride) {
        float4 v = x[i];
        v.x = __uint_as_float(f2tf32(v.x));
        v.y = __uint_as_float(f2tf32(v.y));
        v.z = __uint_as_float(f2tf32(v.z));
        v.w = __uint_as_float(f2tf32(v.w));
        xr[i] = v;
    }
}

// W1cat [4*DI, DO]: rows [0,DI)=sum_r Wself_r ; rows DI+r*DI+d = Wneigh[r][d]. tf32 bits.
__global__ void prep_w1_kernel(const float* __restrict__ Wself, const float* __restrict__ Wneigh,
                               const float* __restrict__ b, float* __restrict__ Wcat,
                               float* __restrict__ bs, int DI, int DO) {
    int total = 4 * DI * DO;
    int stride = gridDim.x * blockDim.x;
    for (int idx = blockIdx.x * blockDim.x + threadIdx.x; idx < total; idx += stride) {
        int k = idx / DO;
        int j = idx - k * DO;
        float v;
        if (k < DI) {
            v = Wself[k * DO + j] + Wself[(DI + k) * DO + j] + Wself[(2 * DI + k) * DO + j];
        } else {
            int r = (k - DI) / DI;
            int d = (k - DI) - r * DI;
            v = Wneigh[((size_t)r * DI + d) * DO + j];
        }
        Wcat[idx] = __uint_as_float(f2tf32(v));
    }
    int idx = blockIdx.x * blockDim.x + threadIdx.x;
    if (idx < DO) bs[idx] = b[idx] + b[DO + idx] + b[2 * DO + idx];
}

// W2t [256, 512]: cols [r*128,..) = Wneigh2_r ; cols [384,512) = sum_r Wself2_r. tf32 bits.
__global__ void prep_w2_kernel(const float* __restrict__ Wself, const float* __restrict__ Wneigh,
                               const float* __restrict__ b, float* __restrict__ Wcat,
                               float* __restrict__ bs) {
    int total = D_HID * 4 * D_OUT;
    int stride = gridDim.x * blockDim.x;
    for (int idx = blockIdx.x * blockDim.x + threadIdx.x; idx < total; idx += stride) {
        int k = idx / (4 * D_OUT);
        int c = idx - k * (4 * D_OUT);
        float v;
        if (c < 3 * D_OUT) {
            int r = c / D_OUT;
            int j = c - r * D_OUT;
            v = Wneigh[((size_t)r * D_HID + k) * D_OUT + j];
        } else {
            int j = c - 3 * D_OUT;
            v = Wself[(size_t)k * D_OUT + j]
              + Wself[((size_t)D_HID + k) * D_OUT + j]
              + Wself[((size_t)2 * D_HID + k) * D_OUT + j];
        }
        Wcat[idx] = __uint_as_float(f2tf32(v));
    }
    int idx = blockIdx.x * blockDim.x + threadIdx.x;
    if (idx < D_OUT) bs[idx] = b[idx] + b[D_OUT + idx] + b[2 * D_OUT + idx];
}

// ---------------- CSR build ----------------
__global__ void cnt_kernel(const int* __restrict__ dst, int* __restrict__ cnt) {
    int e = blockIdx.x * blockDim.x + threadIdx.x;
    if (e >= RELS * EDGES) return;
    int r = e / EDGES;
    atomicAdd(&cnt[r * NODES + dst[e]], 1);
}

__global__ void scan1_kernel(const int* __restrict__ cnt, int* __restrict__ offs,
                             int* __restrict__ bsum) {
    __shared__ int sm[SCAN_B];
    int i = blockIdx.x * SCAN_B + threadIdx.x;
    int v = (i < SCAN_N) ? cnt[i] : 0;
    sm[threadIdx.x] = v;
    __syncthreads();
#pragma unroll
    for (int off = 1; off < SCAN_B; off <<= 1) {
        int t = (threadIdx.x >= off) ? sm[threadIdx.x - off] : 0;
        __syncthreads();
        sm[threadIdx.x] += t;
        __syncthreads();
    }
    int incl = sm[threadIdx.x];
    if (i < SCAN_N) offs[i] = incl - v;
    if (threadIdx.x == SCAN_B - 1) bsum[blockIdx.x] = incl;
}

__global__ void scan2_kernel(int* __restrict__ bsum, int nb) {
    __shared__ int sm[SCAN_B];
    int v = (threadIdx.x < nb) ? bsum[threadIdx.x] : 0;
    sm[threadIdx.x] = v;
    __syncthreads();
#pragma unroll
    for (int off = 1; off < SCAN_B; off <<= 1) {
        int t = (threadIdx.x >= off) ? sm[threadIdx.x - off] : 0;
        __syncthreads();
        sm[threadIdx.x] += t;
        __syncthreads();
    }
    if (threadIdx.x < nb) bsum[threadIdx.x] = sm[threadIdx.x] - v;
}

__global__ void scan3_kernel(int* __restrict__ offs, const int* __restrict__ bsum) {
    int i = blockIdx.x * SCAN_B + threadIdx.x;
    if (i < SCAN_N) offs[i] += bsum[blockIdx.x];
    if (i == 0) offs[SCAN_N] = RELS * EDGES;
}

__global__ void fill_kernel(const int* __restrict__ src, const int* __restrict__ dst,
                            const int* __restrict__ offs, int* __restrict__ cur,
                            int* __restrict__ elist) {
    int e = blockIdx.x * blockDim.x + threadIdx.x;
    if (e >= RELS * EDGES) return;
    int r = e / EDGES;
    int idx = r * NODES + dst[e];
    int pos = offs[idx] + atomicAdd(&cur[idx], 1);
    elist[pos] = src[e];
}

// ---------------- reduce 1: seg[r*NODES+d] = tf32(mean of x[src]) ----------------
__global__ void reduce1_kernel(const float* __restrict__ x, const int* __restrict__ offs,
                               const int* __restrict__ elist, float* __restrict__ seg) {
    int w = (blockIdx.x * blockDim.x + threadIdx.x) >> 5;
    int lane = threadIdx.x & 31;
    if (w >= SCAN_N) return;
    int beg = offs[w], end = offs[w + 1];
    float4 s = make_float4(0.f, 0.f, 0.f, 0.f);
    for (int i = beg; i < end; i += 32) {
        int nid = (i + lane < end) ? elist[i + lane] : 0;
        int cnt = min(32, end - i);
        for (int j = 0; j < cnt; j++) {
            int sid = __shfl_sync(0xffffffffu, nid, j);
            float4 v = __ldg(((const float4*)(x + (size_t)sid * D_IN)) + lane);
            s.x += v.x; s.y += v.y; s.z += v.z; s.w += v.w;
        }
    }
    float sc = 1.f / fmaxf((float)(end - beg), 1.f);
    s.x = __uint_as_float(f2tf32(s.x * sc));
    s.y = __uint_as_float(f2tf32(s.y * sc));
    s.z = __uint_as_float(f2tf32(s.z * sc));
    s.w = __uint_as_float(f2tf32(s.w * sc));
    ((float4*)(seg + (size_t)w * D_IN))[lane] = s;
}

// ---------------- fused reduce 2 + final: one warp per node ----------------
// out[d] = Yself[d] + b2 + sum_r (1/deg_r) * sum_{e in (r,d)} Y[src_e, r*128..]
__global__ void reduce2_final_kernel(const float* __restrict__ Y, const int* __restrict__ offs,
                                     const int* __restrict__ elist, const float* __restrict__ bs,
                                     float* __restrict__ out) {
    int d = (blockIdx.x * blockDim.x + threadIdx.x) >> 5;
    int lane = threadIdx.x & 31;
    if (d >= NODES) return;

    float4 acc = __ldg(((const float4*)(Y + (size_t)d * (4 * D_OUT) + 3 * D_OUT)) + lane);
    float4 bv  = __ldg(((const float4*)bs) + lane);
    acc.x += bv.x; acc.y += bv.y; acc.z += bv.z; acc.w += bv.w;

#pragma unroll
    for (int r = 0; r < RELS; r++) {
        int w = r * NODES + d;
        int beg = offs[w], end = offs[w + 1];
        if (beg == end) continue;
        float4 s = make_float4(0.f, 0.f, 0.f, 0.f);
        for (int i = beg; i < end; i += 32) {
            int nid = (i + lane < end) ? elist[i + lane] : 0;
            int cnt = min(32, end - i);
            for (int j = 0; j < cnt; j++) {
                int sid = __shfl_sync(0xffffffffu, nid, j);
                float4 v = __ldg(((const float4*)(Y + (size_t)sid * (4 * D_OUT) + r * D_OUT)) + lane);
                s.x += v.x; s.y += v.y; s.z += v.z; s.w += v.w;
            }
        }
        float sc = 1.f / (float)(end - beg);
        acc.x += s.x * sc; acc.y += s.y * sc; acc.z += s.z * sc; acc.w += s.w * sc;
    }
    ((float4*)(out + (size_t)d * D_OUT))[lane] = acc;
}

// ---------------- cp.async double-buffered tf32 GEMM, fused concat-A ----------------
#define ASTRIDE 36
#define BSTRIDE 136
#define A_TILE (128 * ASTRIDE)
#define B_TILE (32 * BSTRIDE)
#define GEMM_SMEM ((2 * A_TILE + 2 * B_TILE) * 4)

// doRound: round output to tf32 bits (for h feeding the next GEMM as A)
template <int D>
__global__ __launch_bounds__(256, 2)
void gemm_tf32_kernel(const float* __restrict__ feat, const float* __restrict__ seg,
                      const float* __restrict__ Bw, const float* __restrict__ bias,
                      float* __restrict__ C, int M, int N, int K,
                      int doRelu, int doBias, int doRound) {
    extern __shared__ float smp[];
    float* As = smp;
    float* Bs = smp + 2 * A_TILE;
    const uint32_t As_u = (uint32_t)__cvta_generic_to_shared(As);
    const uint32_t Bs_u = (uint32_t)__cvta_generic_to_shared(Bs);

    const int tid  = threadIdx.x;
    const int lane = tid & 31;
    const int warp = tid >> 5;
    const int warpM = (warp >> 2) * 64;
    const int warpN = (warp & 3) * 32;
    const int block_row = blockIdx.x * 128;
    const int block_col = blockIdx.y * 128;

    const int a_r0 = tid >> 3;          // 0..31
    const int a_c0 = (tid & 7) * 4;     // 0..28
    const int b_r0 = tid >> 5;          // 0..7
    const int b_c0 = (tid & 31) * 4;    // 0..124

    float acc[4][4][4];
#pragma unroll
    for (int i = 0; i < 4; i++)
#pragma unroll
        for (int j = 0; j < 4; j++)
#pragma unroll
            for (int c = 0; c < 4; c++) acc[i][j][c] = 0.f;

    auto load_stage = [&](int buf, int kb) {
        const int chunk = kb / D;
        const int col0 = kb - chunk * D;
        const float* base = (chunk == 0) ? feat : (seg + (size_t)(chunk - 1) * NODES * D);
#pragma unroll
        for (int p = 0; p < 4; p++) {
            int r = p * 32 + a_r0;
            int gr = block_row + r;
            const float* g = base + (size_t)gr * D + col0 + a_c0;
            uint32_t sa = As_u + (uint32_t)(buf * A_TILE + r * ASTRIDE + a_c0) * 4u;
            int sz = (gr < M) ? 16 : 0;
            asm volatile("cp.async.cg.shared.global [%0], [%1], 16, %2;"
                         :: "r"(sa), "l"(g), "r"(sz));
        }
#pragma unroll
        for (int p = 0; p < 4; p++) {
            int r = p * 8 + b_r0;
            const float* g = Bw + (size_t)(kb + r) * N + block_col + b_c0;
            uint32_t sa = Bs_u + (uint32_t)(buf * B_TILE + r * BSTRIDE + b_c0) * 4u;
            asm volatile("cp.async.cg.shared.global [%0], [%1], 16;"
                         :: "r"(sa), "l"(g));
        }
        asm volatile("cp.async.commit_group;");
    };

    const int T = K / 32;
    load_stage(0, 0);

    for (int t = 0; t < T; t++) {
        int buf = t & 1;
        if (t + 1 < T) {
            load_stage(buf ^ 1, (t + 1) * 32);
            asm volatile("cp.async.wait_group 1;");
        } else {
            asm volatile("cp.async.wait_group 0;");
        }
        __syncthreads();

        const float* At = As + buf * A_TILE;
        const float* Bt = Bs + buf * B_TILE;
#pragma unroll
        for (int k8 = 0; k8 < 4; k8++) {
            unsigned a[4][4];
#pragma unroll
            for (int mt = 0; mt < 4; mt++) {
                int row = warpM + mt * 16 + (lane >> 2);
                int col = k8 * 8 + (lane & 3);
                a[mt][0] = __float_as_uint(At[row * ASTRIDE + col]);
                a[mt][1] = __float_as_uint(At[(row + 8) * ASTRIDE + col]);
                a[mt][2] = __float_as_uint(At[row * ASTRIDE + col + 4]);
                a[mt][3] = __float_as_uint(At[(row + 8) * ASTRIDE + col + 4]);
            }
            unsigned b[4][2];
#pragma unroll
            for (int nt = 0; nt < 4; nt++) {
                int cn = warpN + nt * 8 + (lane >> 2);
                int kr = k8 * 8 + (lane & 3);
                b[nt][0] = __float_as_uint(Bt[kr * BSTRIDE + cn]);
                b[nt][1] = __float_as_uint(Bt[(kr + 4) * BSTRIDE + cn]);
            }
#pragma unroll
            for (int mt = 0; mt < 4; mt++)
#pragma unroll
                for (int nt = 0; nt < 4; nt++) {
                    asm volatile(
                        "mma.sync.aligned.m16n8k8.row.col.f32.tf32.tf32.f32 "
                        "{%0,%1,%2,%3}, {%4,%5,%6,%7}, {%8,%9}, {%0,%1,%2,%3};"
                        : "+f"(acc[mt][nt][0]), "+f"(acc[mt][nt][1]),
                          "+f"(acc[mt][nt][2]), "+f"(acc[mt][nt][3])
                        : "r"(a[mt][0]), "r"(a[mt][1]), "r"(a[mt][2]), "r"(a[mt][3]),
                          "r"(b[nt][0]), "r"(b[nt][1]));
                }
        }
        __syncthreads();
    }

#pragma unroll
    for (int mt = 0; mt < 4; mt++) {
#pragma unroll
        for (int nt = 0; nt < 4; nt++) {
            int col = block_col + warpN + nt * 8 + (lane & 3) * 2;
            float bx = doBias ? bias[col] : 0.f;
            float by = doBias ? bias[col + 1] : 0.f;
#pragma unroll
            for (int half = 0; half < 2; half++) {
                int row = block_row + warpM + mt * 16 + (lane >> 2) + half * 8;
                if (row >= M) continue;
                float vx = acc[mt][nt][half * 2 + 0] + bx;
                float vy = acc[mt][nt][half * 2 + 1] + by;
                if (doRelu) { vx = fmaxf(vx, 0.f); vy = fmaxf(vy, 0.f); }
                if (doRound) {
                    vx = __uint_as_float(f2tf32(vx));
                    vy = __uint_as_float(f2tf32(vy));
                }
                *(float2*)(C + (size_t)row * N + col) = make_float2(vx, vy);
            }
        }
    }
}

// ---------------- launch ----------------
extern "C" void kernel_launch(void* const* d_in, const int* in_sizes, int n_in,
                              void* d_out, int out_size) {
    const float* x      = (const float*)d_in[0];
    const int*   src    = (const int*)  d_in[1];
    const int*   dst    = (const int*)  d_in[2];
    const float* Wself1 = (const float*)d_in[3];
    const float* Wneigh1= (const float*)d_in[4];
    const float* b1     = (const float*)d_in[5];
    const float* Wself2 = (const float*)d_in[6];
    const float* Wneigh2= (const float*)d_in[7];
    const float* b2     = (const float*)d_in[8];
    float* out = (float*)d_out;

    float *xr, *seg1, *h, *Y, *W1, *W2t, *b1s, *b2s;
    int *csr, *offs, *bsum, *elist;
    cudaGetSymbolAddress((void**)&xr,   g_xr);
    cudaGetSymbolAddress((void**)&seg1, g_seg1);
    cudaGetSymbolAddress((void**)&h,    g_h);
    cudaGetSymbolAddress((void**)&Y,    g_Y);
    cudaGetSymbolAddress((void**)&csr,  g_csr);
    cudaGetSymbolAddress((void**)&offs, g_offs);
    cudaGetSymbolAddress((void**)&bsum, g_bsum);
    cudaGetSymbolAddress((void**)&elist,g_elist);
    cudaGetSymbolAddress((void**)&W1,   g_W1);
    cudaGetSymbolAddress((void**)&W2t,  g_W2t);
    cudaGetSymbolAddress((void**)&b1s,  g_b1s);
    cudaGetSymbolAddress((void**)&b2s,  g_b2s);

    cudaFuncSetAttribute(gemm_tf32_kernel<D_IN>,
                         cudaFuncAttributeMaxDynamicSharedMemorySize, GEMM_SMEM);
    cudaFuncSetAttribute(gemm_tf32_kernel<D_HID>,
                         cudaFuncAttributeMaxDynamicSharedMemorySize, GEMM_SMEM);

    int* cnt = csr;
    int* cur = csr + SCAN_N;

    // ---- zero CSR counters ----
    zero_i<<<(2 * SCAN_N + 255) / 256, 256>>>(csr, 2 * SCAN_N);

    // ---- weights (tf32), bias sums, rounded x ----
    prep_w1_kernel<<<(4 * D_IN * D_HID + 255) / 256, 256>>>(Wself1, Wneigh1, b1, W1, b1s, D_IN, D_HID);
    prep_w2_kernel<<<(D_HID * 4 * D_OUT + 255) / 256, 256>>>(Wself2, Wneigh2, b2, W2t, b2s);
    round_x_kernel<<<4096, 256>>>((const float4*)x, (float4*)xr, (long)NODES * D_IN / 4);

    // ---- CSR build ----
    cnt_kernel<<<(RELS * EDGES + 255) / 256, 256>>>(dst, cnt);
    scan1_kernel<<<SCAN_BLOCKS, SCAN_B>>>(cnt, offs, bsum);
    scan2_kernel<<<1, SCAN_B>>>(bsum, SCAN_BLOCKS);
    scan3_kernel<<<SCAN_BLOCKS, SCAN_B>>>(offs, bsum);
    fill_kernel<<<(RELS * EDGES + 255) / 256, 256>>>(src, dst, offs, cur, elist);

    const int reduce_blocks = (SCAN_N * 32 + 255) / 256;
    const int mblocks = (NODES + 127) / 128;

    // ---- layer 1: means (rounded) -> seg1, fused-concat GEMM -> h (relu+bias+round) ----
    reduce1_kernel<<<reduce_blocks, 256>>>(x, offs, elist, seg1);
    {
        dim3 grid(mblocks, D_HID / 128);
        gemm_tf32_kernel<D_IN><<<grid, 256, GEMM_SMEM>>>(xr, seg1, W1, b1s, h,
                                                         NODES, D_HID, 4 * D_IN, 1, 1, 1);
    }

    // ---- layer 2: transform-first GEMM -> Y, then fused reduce+final -> out ----
    {
        dim3 grid(mblocks, (4 * D_OUT) / 128);
        gemm_tf32_kernel<D_HID><<<grid, 256, GEMM_SMEM>>>(h, nullptr, W2t, nullptr, Y,
                                                          NODES, 4 * D_OUT, D_HID, 0, 0, 0);
    }
    reduce2_final_kernel<<<(NODES * 32 + 255) / 256, 256>>>(Y, offs, elist, b2s, out);
}

// round 6
// speedup vs baseline: 1.0586x; 1.0586x over previous
#include <cuda_runtime.h>
#include <cuda_fp16.h>
#include <cstdint>

// ---------------- problem constants ----------------
#define NODES 50000
#define RELS  3
#define EDGES 600000
#define D_IN  128
#define D_HID 256
#define D_OUT 128

#define SCAN_N (RELS * NODES)          // 150000 segments
#define SCAN_B 512
#define SCAN_BLOCKS ((SCAN_N + SCAN_B - 1) / SCAN_B)   // 293

// ---------------- scratch ----------------
__device__ float  g_xr  [(size_t)NODES * D_IN];           // 25.6 MB  x rounded to tf32 (GEMM A)
__device__ __half g_xh  [(size_t)NODES * D_IN];           // 12.8 MB  x in fp16 (gather)
__device__ float  g_seg1[(size_t)RELS * NODES * D_IN];    // 76.8 MB  means (tf32 bits)
__device__ float  g_h   [(size_t)NODES * D_HID];          // 51.2 MB  (tf32 bits)
__device__ __half g_Yh  [(size_t)NODES * 3 * D_OUT];      // 38.4 MB  neighbor-transformed, fp16
__device__ float  g_Ys  [(size_t)NODES * D_OUT];          // 25.6 MB  self-transformed, fp32
__device__ int    g_cnt [SCAN_N];
__device__ int    g_offs[SCAN_N + 1];
__device__ int    g_bsum[SCAN_B];
__device__ int    g_elist[(size_t)RELS * EDGES];          // 7.2 MB
__device__ float  g_W1  [4 * D_IN * D_HID];               // 512 x 256 (tf32 bits)
__device__ float  g_W2t [D_HID * 4 * D_OUT];              // 256 x 512 (tf32 bits)
__device__ float  g_b1s [D_HID];
__device__ float  g_b2s [D_OUT];

__device__ __forceinline__ unsigned f2tf32(float x) {
    unsigned r;
    asm("cvt.rna.tf32.f32 %0, %1;" : "=r"(r) : "f"(x));
    return r;
}

// ---------------- utility ----------------
__global__ void zero_i(int* __restrict__ p, int n) {
    int i = blockIdx.x * blockDim.x + threadIdx.x;
    if (i < n) p[i] = 0;
}

// x -> xr (tf32 bits) and xh (fp16), one pass
__global__ void prep_x_kernel(const float4* __restrict__ x, float4* __restrict__ xr,
                              __half2* __restrict__ xh, long n4) {
    long stride = (long)gridDim.x * blockDim.x;
    for (long i = (long)blockIdx.x * blockDim.x + threadIdx.x; i < n4; i += stride) {
        float4 v = x[i];
        float4 t;
        t.x = __uint_as_float(f2tf32(v.x));
        t.y = __uint_as_float(f2tf32(v.y));
        t.z = __uint_as_float(f2tf32(v.z));
        t.w = __uint_as_float(f2tf32(v.w));
        xr[i] = t;
        xh[i * 2 + 0] = __floats2half2_rn(v.x, v.y);
        xh[i * 2 + 1] = __floats2half2_rn(v.z, v.w);
    }
}

// W1cat [4*DI, DO]: rows [0,DI)=sum_r Wself_r ; rows DI+r*DI+d = Wneigh[r][d]. tf32 bits.
__global__ void prep_w1_kernel(const float* __restrict__ Wself, const float* __restrict__ Wneigh,
                               const float* __restrict__ b, float* __restrict__ Wcat,
                               float* __restrict__ bs, int DI, int DO) {
    int total = 4 * DI * DO;
    int stride = gridDim.x * blockDim.x;
    for (int idx = blockIdx.x * blockDim.x + threadIdx.x; idx < total; idx += stride) {
        int k = idx / DO;
        int j = idx - k * DO;
        float v;
        if (k < DI) {
            v = Wself[k * DO + j] + Wself[(DI + k) * DO + j] + Wself[(2 * DI + k) * DO + j];
        } else {
            int r = (k - DI) / DI;
            int d = (k - DI) - r * DI;
            v = Wneigh[((size_t)r * DI + d) * DO + j];
        }
        Wcat[idx] = __uint_as_float(f2tf32(v));
    }
    int idx = blockIdx.x * blockDim.x + threadIdx.x;
    if (idx < DO) bs[idx] = b[idx] + b[DO + idx] + b[2 * DO + idx];
}

// W2t [256, 512]: cols [r*128,..) = Wneigh2_r ; cols [384,512) = sum_r Wself2_r. tf32 bits.
__global__ void prep_w2_kernel(const float* __restrict__ Wself, const float* __restrict__ Wneigh,
                               const float* __restrict__ b, float* __restrict__ Wcat,
                               float* __restrict__ bs) {
    int total = D_HID * 4 * D_OUT;
    int stride = gridDim.x * blockDim.x;
    for (int idx = blockIdx.x * blockDim.x + threadIdx.x; idx < total; idx += stride) {
        int k = idx / (4 * D_OUT);
        int c = idx - k * (4 * D_OUT);
        float v;
        if (c < 3 * D_OUT) {
            int r = c / D_OUT;
            int j = c - r * D_OUT;
            v = Wneigh[((size_t)r * D_HID + k) * D_OUT + j];
        } else {
            int j = c - 3 * D_OUT;
            v = Wself[(size_t)k * D_OUT + j]
              + Wself[((size_t)D_HID + k) * D_OUT + j]
              + Wself[((size_t)2 * D_HID + k) * D_OUT + j];
        }
        Wcat[idx] = __uint_as_float(f2tf32(v));
    }
    int idx = blockIdx.x * blockDim.x + threadIdx.x;
    if (idx < D_OUT) bs[idx] = b[idx] + b[D_OUT + idx] + b[2 * D_OUT + idx];
}

// ---------------- CSR build ----------------
__global__ void cnt_kernel(const int* __restrict__ dst, int* __restrict__ cnt) {
    int e = blockIdx.x * blockDim.x + threadIdx.x;
    if (e >= RELS * EDGES) return;
    int r = e / EDGES;
    atomicAdd(&cnt[r * NODES + dst[e]], 1);
}

__global__ void scan1_kernel(const int* __restrict__ cnt, int* __restrict__ offs,
                             int* __restrict__ bsum) {
    __shared__ int sm[SCAN_B];
    int i = blockIdx.x * SCAN_B + threadIdx.x;
    int v = (i < SCAN_N) ? cnt[i] : 0;
    sm[threadIdx.x] = v;
    __syncthreads();
#pragma unroll
    for (int off = 1; off < SCAN_B; off <<= 1) {
        int t = (threadIdx.x >= off) ? sm[threadIdx.x - off] : 0;
        __syncthreads();
        sm[threadIdx.x] += t;
        __syncthreads();
    }
    int incl = sm[threadIdx.x];
    if (i < SCAN_N) offs[i] = incl - v;
    if (threadIdx.x == SCAN_B - 1) bsum[blockIdx.x] = incl;
}

__global__ void scan2_kernel(int* __restrict__ bsum, int nb) {
    __shared__ int sm[SCAN_B];
    int v = (threadIdx.x < nb) ? bsum[threadIdx.x] : 0;
    sm[threadIdx.x] = v;
    __syncthreads();
#pragma unroll
    for (int off = 1; off < SCAN_B; off <<= 1) {
        int t = (threadIdx.x >= off) ? sm[threadIdx.x - off] : 0;
        __syncthreads();
        sm[threadIdx.x] += t;
        __syncthreads();
    }
    if (threadIdx.x < nb) bsum[threadIdx.x] = sm[threadIdx.x] - v;
}

__global__ void scan3_kernel(int* __restrict__ offs, const int* __restrict__ bsum) {
    int i = blockIdx.x * SCAN_B + threadIdx.x;
    if (i < SCAN_N) offs[i] += bsum[blockIdx.x];
    if (i == 0) offs[SCAN_N] = RELS * EDGES;
}

// uses cnt as the per-segment cursor (atomicSub); cnt is dead afterwards
__global__ void fill_kernel(const int* __restrict__ src, const int* __restrict__ dst,
                            const int* __restrict__ offs, int* __restrict__ cnt,
                            int* __restrict__ elist) {
    int e = blockIdx.x * blockDim.x + threadIdx.x;
    if (e >= RELS * EDGES) return;
    int r = e / EDGES;
    int idx = r * NODES + dst[e];
    int pos = offs[idx] + (atomicSub(&cnt[idx], 1) - 1);
    elist[pos] = src[e];
}

// ---------------- reduce 1: seg[r*NODES+d] = tf32(mean of fp16 x[src]) ----------------
__global__ void reduce1_kernel(const __half* __restrict__ xh, const int* __restrict__ offs,
                               const int* __restrict__ elist, float* __restrict__ seg) {
    int w = (blockIdx.x * blockDim.x + threadIdx.x) >> 5;
    int lane = threadIdx.x & 31;
    if (w >= SCAN_N) return;
    int beg = offs[w], end = offs[w + 1];
    float4 s = make_float4(0.f, 0.f, 0.f, 0.f);
    for (int i = beg; i < end; i += 32) {
        int nid = (i + lane < end) ? elist[i + lane] : 0;
        int cnt = min(32, end - i);
        for (int j = 0; j < cnt; j++) {
            int sid = __shfl_sync(0xffffffffu, nid, j);
            uint2 v = __ldg(((const uint2*)(xh + (size_t)sid * D_IN)) + lane);
            __half2 h0 = *reinterpret_cast<__half2*>(&v.x);
            __half2 h1 = *reinterpret_cast<__half2*>(&v.y);
            float2 f0 = __half22float2(h0);
            float2 f1 = __half22float2(h1);
            s.x += f0.x; s.y += f0.y; s.z += f1.x; s.w += f1.y;
        }
    }
    float sc = 1.f / fmaxf((float)(end - beg), 1.f);
    s.x = __uint_as_float(f2tf32(s.x * sc));
    s.y = __uint_as_float(f2tf32(s.y * sc));
    s.z = __uint_as_float(f2tf32(s.z * sc));
    s.w = __uint_as_float(f2tf32(s.w * sc));
    ((float4*)(seg + (size_t)w * D_IN))[lane] = s;
}

// ---------------- fused reduce 2 + final: one warp per node ----------------
// out[d] = Ys[d] + b2 + sum_r (1/deg_r) * sum_{e in (r,d)} Yh[src_e, r*128..]
__global__ void reduce2_final_kernel(const __half* __restrict__ Yh, const float* __restrict__ Ys,
                                     const int* __restrict__ offs, const int* __restrict__ elist,
                                     const float* __restrict__ bs, float* __restrict__ out) {
    int d = (blockIdx.x * blockDim.x + threadIdx.x) >> 5;
    int lane = threadIdx.x & 31;
    if (d >= NODES) return;

    float4 acc = __ldg(((const float4*)(Ys + (size_t)d * D_OUT)) + lane);
    float4 bv  = __ldg(((const float4*)bs) + lane);
    acc.x += bv.x; acc.y += bv.y; acc.z += bv.z; acc.w += bv.w;

#pragma unroll
    for (int r = 0; r < RELS; r++) {
        int w = r * NODES + d;
        int beg = offs[w], end = offs[w + 1];
        if (beg == end) continue;
        float4 s = make_float4(0.f, 0.f, 0.f, 0.f);
        for (int i = beg; i < end; i += 32) {
            int nid = (i + lane < end) ? elist[i + lane] : 0;
            int cnt = min(32, end - i);
            for (int j = 0; j < cnt; j++) {
                int sid = __shfl_sync(0xffffffffu, nid, j);
                uint2 v = __ldg(((const uint2*)(Yh + (size_t)sid * (3 * D_OUT) + r * D_OUT)) + lane);
                __half2 h0 = *reinterpret_cast<__half2*>(&v.x);
                __half2 h1 = *reinterpret_cast<__half2*>(&v.y);
                float2 f0 = __half22float2(h0);
                float2 f1 = __half22float2(h1);
                s.x += f0.x; s.y += f0.y; s.z += f1.x; s.w += f1.y;
            }
        }
        float sc = 1.f / (float)(end - beg);
        acc.x += s.x * sc; acc.y += s.y * sc; acc.z += s.z * sc; acc.w += s.w * sc;
    }
    ((float4*)(out + (size_t)d * D_OUT))[lane] = acc;
}

// ---------------- cp.async 3-stage tf32 GEMM, fused concat-A, split fp16/fp32 out ----------------
#define ASTRIDE 36
#define BSTRIDE 136
#define A_TILE (128 * ASTRIDE)
#define B_TILE (32 * BSTRIDE)
#define NSTAGE 3
#define GEMM_SMEM (NSTAGE * (A_TILE + B_TILE) * 4)

// cols < halfCols -> Ch (fp16, row stride halfCols); cols >= halfCols -> Cf (fp32, stride N-halfCols)
template <int D>
__global__ __launch_bounds__(256, 2)
void gemm_tf32_kernel(const float* __restrict__ feat, const float* __restrict__ seg,
                      const float* __restrict__ Bw, const float* __restrict__ bias,
                      float* __restrict__ Cf, __half* __restrict__ Ch,
                      int M, int N, int K, int halfCols,
                      int doRelu, int doBias, int doRound) {
    extern __shared__ float smp[];
    float* As = smp;
    float* Bs = smp + NSTAGE * A_TILE;
    const uint32_t As_u = (uint32_t)__cvta_generic_to_shared(As);
    const uint32_t Bs_u = (uint32_t)__cvta_generic_to_shared(Bs);

    const int tid  = threadIdx.x;
    const int lane = tid & 31;
    const int warp = tid >> 5;
    const int warpM = (warp >> 2) * 64;
    const int warpN = (warp & 3) * 32;
    const int block_row = blockIdx.x * 128;
    const int block_col = blockIdx.y * 128;

    const int a_r0 = tid >> 3;          // 0..31
    const int a_c0 = (tid & 7) * 4;     // 0..28
    const int b_r0 = tid >> 5;          // 0..7
    const int b_c0 = (tid & 31) * 4;    // 0..124

    float acc[4][4][4];
#pragma unroll
    for (int i = 0; i < 4; i++)
#pragma unroll
        for (int j = 0; j < 4; j++)
#pragma unroll
            for (int c = 0; c < 4; c++) acc[i][j][c] = 0.f;

    auto load_stage = [&](int buf, int kb) {
        const int chunk = kb / D;
        const int col0 = kb - chunk * D;
        const float* base = (chunk == 0) ? feat : (seg + (size_t)(chunk - 1) * NODES * D);
#pragma unroll
        for (int p = 0; p < 4; p++) {
            int r = p * 32 + a_r0;
            int gr = block_row + r;
            const float* g = base + (size_t)gr * D + col0 + a_c0;
            uint32_t sa = As_u + (uint32_t)(buf * A_TILE + r * ASTRIDE + a_c0) * 4u;
            int sz = (gr < M) ? 16 : 0;
            asm volatile("cp.async.cg.shared.global [%0], [%1], 16, %2;"
                         :: "r"(sa), "l"(g), "r"(sz));
        }
#pragma unroll
        for (int p = 0; p < 4; p++) {
            int r = p * 8 + b_r0;
            const float* g = Bw + (size_t)(kb + r) * N + block_col + b_c0;
            uint32_t sa = Bs_u + (uint32_t)(buf * B_TILE + r * BSTRIDE + b_c0) * 4u;
            asm volatile("cp.async.cg.shared.global [%0], [%1], 16;"
                         :: "r"(sa), "l"(g));
        }
        asm volatile("cp.async.commit_group;");
    };

    const int T = K / 32;
    load_stage(0, 0);
    load_stage(1, 32);

    for (int t = 0; t < T; t++) {
        if (t + 1 < T) {
            asm volatile("cp.async.wait_group 1;");
        } else {
            asm volatile("cp.async.wait_group 0;");
        }
        __syncthreads();
        if (t + 2 < T) load_stage((t + 2) % NSTAGE, (t + 2) * 32);

        int buf = t % NSTAGE;
        const float* At = As + buf * A_TILE;
        const float* Bt = Bs + buf * B_TILE;
#pragma unroll
        for (int k8 = 0; k8 < 4; k8++) {
            unsigned a[4][4];
#pragma unroll
            for (int mt = 0; mt < 4; mt++) {
                int row = warpM + mt * 16 + (lane >> 2);
                int col = k8 * 8 + (lane & 3);
                a[mt][0] = __float_as_uint(At[row * ASTRIDE + col]);
                a[mt][1] = __float_as_uint(At[(row + 8) * ASTRIDE + col]);
                a[mt][2] = __float_as_uint(At[row * ASTRIDE + col + 4]);
                a[mt][3] = __float_as_uint(At[(row + 8) * ASTRIDE + col + 4]);
            }
            unsigned b[4][2];
#pragma unroll
            for (int nt = 0; nt < 4; nt++) {
                int cn = warpN + nt * 8 + (lane >> 2);
                int kr = k8 * 8 + (lane & 3);
                b[nt][0] = __float_as_uint(Bt[kr * BSTRIDE + cn]);
                b[nt][1] = __float_as_uint(Bt[(kr + 4) * BSTRIDE + cn]);
            }
#pragma unroll
            for (int mt = 0; mt < 4; mt++)
#pragma unroll
                for (int nt = 0; nt < 4; nt++) {
                    asm volatile(
                        "mma.sync.aligned.m16n8k8.row.col.f32.tf32.tf32.f32 "
                        "{%0,%1,%2,%3}, {%4,%5,%6,%7}, {%8,%9}, {%0,%1,%2,%3};"
                        : "+f"(acc[mt][nt][0]), "+f"(acc[mt][nt][1]),
                          "+f"(acc[mt][nt][2]), "+f"(acc[mt][nt][3])
                        : "r"(a[mt][0]), "r"(a[mt][1]), "r"(a[mt][2]), "r"(a[mt][3]),
                          "r"(b[nt][0]), "r"(b[nt][1]));
                }
        }
        __syncthreads();
    }

    const int fStride = N - halfCols;
#pragma unroll
    for (int mt = 0; mt < 4; mt++) {
#pragma unroll
        for (int nt = 0; nt < 4; nt++) {
            int col = block_col + warpN + nt * 8 + (lane & 3) * 2;
            float bx = doBias ? bias[col] : 0.f;
            float by = doBias ? bias[col + 1] : 0.f;
#pragma unroll
            for (int half = 0; half < 2; half++) {
                int row = block_row + warpM + mt * 16 + (lane >> 2) + half * 8;
                if (row >= M) continue;
                float vx = acc[mt][nt][half * 2 + 0] + bx;
                float vy = acc[mt][nt][half * 2 + 1] + by;
                if (doRelu) { vx = fmaxf(vx, 0.f); vy = fmaxf(vy, 0.f); }
                if (col < halfCols) {
                    *(__half2*)(Ch + (size_t)row * halfCols + col) = __floats2half2_rn(vx, vy);
                } else {
                    if (doRound) {
                        vx = __uint_as_float(f2tf32(vx));
                        vy = __uint_as_float(f2tf32(vy));
                    }
                    *(float2*)(Cf + (size_t)row * fStride + (col - halfCols)) = make_float2(vx, vy);
                }
            }
        }
    }
}

// ---------------- launch ----------------
extern "C" void kernel_launch(void* const* d_in, const int* in_sizes, int n_in,
                              void* d_out, int out_size) {
    const float* x      = (const float*)d_in[0];
    const int*   src    = (const int*)  d_in[1];
    const int*   dst    = (const int*)  d_in[2];
    const float* Wself1 = (const float*)d_in[3];
    const float* Wneigh1= (const float*)d_in[4];
    const float* b1     = (const float*)d_in[5];
    const float* Wself2 = (const float*)d_in[6];
    const float* Wneigh2= (const float*)d_in[7];
    const float* b2     = (const float*)d_in[8];
    float* out = (float*)d_out;

    float *xr, *seg1, *h, *Ys, *W1, *W2t, *b1s, *b2s;
    __half *xh, *Yh;
    int *cnt, *offs, *bsum, *elist;
    cudaGetSymbolAddress((void**)&xr,   g_xr);
    cudaGetSymbolAddress((void**)&xh,   g_xh);
    cudaGetSymbolAddress((void**)&seg1, g_seg1);
    cudaGetSymbolAddress((void**)&h,    g_h);
    cudaGetSymbolAddress((void**)&Yh,   g_Yh);
    cudaGetSymbolAddress((void**)&Ys,   g_Ys);
    cudaGetSymbolAddress((void**)&cnt,  g_cnt);
    cudaGetSymbolAddress((void**)&offs, g_offs);
    cudaGetSymbolAddress((void**)&bsum, g_bsum);
    cudaGetSymbolAddress((void**)&elist,g_elist);
    cudaGetSymbolAddress((void**)&W1,   g_W1);
    cudaGetSymbolAddress((void**)&W2t,  g_W2t);
    cudaGetSymbolAddress((void**)&b1s,  g_b1s);
    cudaGetSymbolAddress((void**)&b2s,  g_b2s);

    cudaFuncSetAttribute(gemm_tf32_kernel<D_IN>,
                         cudaFuncAttributeMaxDynamicSharedMemorySize, GEMM_SMEM);
    cudaFuncSetAttribute(gemm_tf32_kernel<D_HID>,
                         cudaFuncAttributeMaxDynamicSharedMemorySize, GEMM_SMEM);

    // ---- zero CSR counters ----
    zero_i<<<(SCAN_N + 255) / 256, 256>>>(cnt, SCAN_N);

    // ---- weights (tf32), bias sums, x copies ----
    prep_w1_kernel<<<(4 * D_IN * D_HID + 255) / 256, 256>>>(Wself1, Wneigh1, b1, W1, b1s, D_IN, D_HID);
    prep_w2_kernel<<<(D_HID * 4 * D_OUT + 255) / 256, 256>>>(Wself2, Wneigh2, b2, W2t, b2s);
    prep_x_kernel<<<4096, 256>>>((const float4*)x, (float4*)xr, (__half2*)xh,
                                 (long)NODES * D_IN / 4);

    // ---- CSR build ----
    cnt_kernel<<<(RELS * EDGES + 255) / 256, 256>>>(dst, cnt);
    scan1_kernel<<<SCAN_BLOCKS, SCAN_B>>>(cnt, offs, bsum);
    scan2_kernel<<<1, SCAN_B>>>(bsum, SCAN_BLOCKS);
    scan3_kernel<<<SCAN_BLOCKS, SCAN_B>>>(offs, bsum);
    fill_kernel<<<(RELS * EDGES + 255) / 256, 256>>>(src, dst, offs, cnt, elist);

    const int reduce_blocks = (SCAN_N * 32 + 255) / 256;
    const int mblocks = (NODES + 127) / 128;

    // ---- layer 1: fp16-gather means -> seg1, fused-concat GEMM -> h (relu+bias+round) ----
    reduce1_kernel<<<reduce_blocks, 256>>>(xh, offs, elist, seg1);
    {
        dim3 grid(mblocks, D_HID / 128);
        gemm_tf32_kernel<D_IN><<<grid, 256, GEMM_SMEM>>>(xr, seg1, W1, b1s, h, nullptr,
                                                         NODES, D_HID, 4 * D_IN, 0, 1, 1, 1);
    }

    // ---- layer 2: GEMM -> [Yh fp16 | Ys fp32], fused reduce+final -> out ----
    {
        dim3 grid(mblocks, (4 * D_OUT) / 128);
        gemm_tf32_kernel<D_HID><<<grid, 256, GEMM_SMEM>>>(h, nullptr, W2t, nullptr, Ys, Yh,
                                                          NODES, 4 * D_OUT, D_HID,
                                                          3 * D_OUT, 0, 0, 0);
    }
    reduce2_final_kernel<<<(NODES * 32 + 255) / 256, 256>>>(Yh, Ys, offs, elist, b2s, out);
}

// round 7
// speedup vs baseline: 1.2160x; 1.1487x over previous
#include <cuda_runtime.h>
#include <cuda_fp16.h>
#include <cstdint>

// ---------------- problem constants ----------------
#define NODES 50000
#define RELS  3
#define EDGES 600000
#define D_IN  128
#define D_HID 256
#define D_OUT 128

#define SCAN_N (RELS * NODES)          // 150000 segments
#define SCAN_B 512
#define SCAN_BLOCKS ((SCAN_N + SCAN_B - 1) / SCAN_B)   // 293

// ---------------- scratch ----------------
__device__ __half g_xh  [(size_t)NODES * D_IN];           // 12.8 MB  x fp16 (gather + GEMM1 A)
__device__ __half g_seg1[(size_t)RELS * NODES * D_IN];    // 38.4 MB  means fp16
__device__ __half g_h   [(size_t)NODES * D_HID];          // 25.6 MB  hidden fp16 (GEMM2 A)
__device__ __half g_Yh  [(size_t)NODES * 3 * D_OUT];      // 38.4 MB  neighbor-transformed fp16
__device__ float  g_Ys  [(size_t)NODES * D_OUT];          // 25.6 MB  self-transformed fp32
__device__ int    g_cnt [SCAN_N];
__device__ int    g_offs[SCAN_N + 1];
__device__ int    g_bsum[SCAN_B];
__device__ int    g_elist[(size_t)RELS * EDGES];          // 7.2 MB
__device__ __half g_W1h [D_HID * (4 * D_IN)];             // [256][512] fp16, transposed
__device__ __half g_W2h [(4 * D_OUT) * D_HID];            // [512][256] fp16, transposed
__device__ float  g_b1s [D_HID];
__device__ float  g_b2s [D_OUT];

// ---------------- utility ----------------
__global__ void zero_i(int* __restrict__ p, int n) {
    int i = blockIdx.x * blockDim.x + threadIdx.x;
    if (i < n) p[i] = 0;
}

// x -> xh (fp16)
__global__ void prep_x_kernel(const float4* __restrict__ x, __half2* __restrict__ xh, long n4) {
    long stride = (long)gridDim.x * blockDim.x;
    for (long i = (long)blockIdx.x * blockDim.x + threadIdx.x; i < n4; i += stride) {
        float4 v = x[i];
        xh[i * 2 + 0] = __floats2half2_rn(v.x, v.y);
        xh[i * 2 + 1] = __floats2half2_rn(v.z, v.w);
    }
}

// W1h [256][512] fp16: W1h[j][k] = (k<128 ? sum_r Wself1[r][k][j] : Wneigh1[r][d][j]) with
// k = 128 + r*128 + d. Also b1s[j] = sum_r b1[r][j].
__global__ void prep_w1_kernel(const float* __restrict__ Wself, const float* __restrict__ Wneigh,
                               const float* __restrict__ b, __half* __restrict__ Wt,
                               float* __restrict__ bs) {
    int total = D_HID * 4 * D_IN;       // 256*512
    int stride = gridDim.x * blockDim.x;
    for (int idx = blockIdx.x * blockDim.x + threadIdx.x; idx < total; idx += stride) {
        int j = idx / (4 * D_IN);
        int k = idx - j * (4 * D_IN);
        float v;
        if (k < D_IN) {
            v = Wself[(size_t)k * D_HID + j]
              + Wself[((size_t)D_IN + k) * D_HID + j]
              + Wself[((size_t)2 * D_IN + k) * D_HID + j];
        } else {
            int r = (k - D_IN) / D_IN;
            int d = (k - D_IN) - r * D_IN;
            v = Wneigh[((size_t)r * D_IN + d) * D_HID + j];
        }
        Wt[idx] = __float2half_rn(v);
    }
    int idx = blockIdx.x * blockDim.x + threadIdx.x;
    if (idx < D_HID) bs[idx] = b[idx] + b[D_HID + idx] + b[2 * D_HID + idx];
}

// W2h [512][256] fp16: row c<384 -> Wneigh2[r][k][j] (c=r*128+j); row c>=384 -> sum_r Wself2[r][k][c-384].
__global__ void prep_w2_kernel(const float* __restrict__ Wself, const float* __restrict__ Wneigh,
                               const float* __restrict__ b, __half* __restrict__ Wt,
                               float* __restrict__ bs) {
    int total = (4 * D_OUT) * D_HID;    // 512*256
    int stride = gridDim.x * blockDim.x;
    for (int idx = blockIdx.x * blockDim.x + threadIdx.x; idx < total; idx += stride) {
        int c = idx / D_HID;
        int k = idx - c * D_HID;
        float v;
        if (c < 3 * D_OUT) {
            int r = c / D_OUT;
            int j = c - r * D_OUT;
            v = Wneigh[((size_t)r * D_HID + k) * D_OUT + j];
        } else {
            int j = c - 3 * D_OUT;
            v = Wself[(size_t)k * D_OUT + j]
              + Wself[((size_t)D_HID + k) * D_OUT + j]
              + Wself[((size_t)2 * D_HID + k) * D_OUT + j];
        }
        Wt[idx] = __float2half_rn(v);
    }
    int idx = blockIdx.x * blockDim.x + threadIdx.x;
    if (idx < D_OUT) bs[idx] = b[idx] + b[D_OUT + idx] + b[2 * D_OUT + idx];
}

// ---------------- CSR build ----------------
__global__ void cnt_kernel(const int* __restrict__ dst, int* __restrict__ cnt) {
    int e = blockIdx.x * blockDim.x + threadIdx.x;
    if (e >= RELS * EDGES) return;
    int r = e / EDGES;
    atomicAdd(&cnt[r * NODES + dst[e]], 1);
}

__global__ void scan1_kernel(const int* __restrict__ cnt, int* __restrict__ offs,
                             int* __restrict__ bsum) {
    __shared__ int sm[SCAN_B];
    int i = blockIdx.x * SCAN_B + threadIdx.x;
    int v = (i < SCAN_N) ? cnt[i] : 0;
    sm[threadIdx.x] = v;
    __syncthreads();
#pragma unroll
    for (int off = 1; off < SCAN_B; off <<= 1) {
        int t = (threadIdx.x >= off) ? sm[threadIdx.x - off] : 0;
        __syncthreads();
        sm[threadIdx.x] += t;
        __syncthreads();
    }
    int incl = sm[threadIdx.x];
    if (i < SCAN_N) offs[i] = incl - v;
    if (threadIdx.x == SCAN_B - 1) bsum[blockIdx.x] = incl;
}

__global__ void scan2_kernel(int* __restrict__ bsum, int nb) {
    __shared__ int sm[SCAN_B];
    int v = (threadIdx.x < nb) ? bsum[threadIdx.x] : 0;
    sm[threadIdx.x] = v;
    __syncthreads();
#pragma unroll
    for (int off = 1; off < SCAN_B; off <<= 1) {
        int t = (threadIdx.x >= off) ? sm[threadIdx.x - off] : 0;
        __syncthreads();
        sm[threadIdx.x] += t;
        __syncthreads();
    }
    if (threadIdx.x < nb) bsum[threadIdx.x] = sm[threadIdx.x] - v;
}

__global__ void scan3_kernel(int* __restrict__ offs, const int* __restrict__ bsum) {
    int i = blockIdx.x * SCAN_B + threadIdx.x;
    if (i < SCAN_N) offs[i] += bsum[blockIdx.x];
    if (i == 0) offs[SCAN_N] = RELS * EDGES;
}

// uses cnt as cursor (atomicSub); cnt dead afterwards
__global__ void fill_kernel(const int* __restrict__ src, const int* __restrict__ dst,
                            const int* __restrict__ offs, int* __restrict__ cnt,
                            int* __restrict__ elist) {
    int e = blockIdx.x * blockDim.x + threadIdx.x;
    if (e >= RELS * EDGES) return;
    int r = e / EDGES;
    int idx = r * NODES + dst[e];
    int pos = offs[idx] + (atomicSub(&cnt[idx], 1) - 1);
    elist[pos] = src[e];
}

// ---------------- reduce 1: seg1[r*NODES+d] = fp16(mean of fp16 x[src]) ----------------
__global__ void reduce1_kernel(const __half* __restrict__ xh, const int* __restrict__ offs,
                               const int* __restrict__ elist, __half* __restrict__ seg) {
    int w = (blockIdx.x * blockDim.x + threadIdx.x) >> 5;
    int lane = threadIdx.x & 31;
    if (w >= SCAN_N) return;
    int beg = offs[w], end = offs[w + 1];
    float4 s = make_float4(0.f, 0.f, 0.f, 0.f);
    for (int i = beg; i < end; i += 32) {
        int nid = (i + lane < end) ? elist[i + lane] : 0;
        int cnt = min(32, end - i);
        for (int j = 0; j < cnt; j++) {
            int sid = __shfl_sync(0xffffffffu, nid, j);
            uint2 v = __ldg(((const uint2*)(xh + (size_t)sid * D_IN)) + lane);
            float2 f0 = __half22float2(*reinterpret_cast<__half2*>(&v.x));
            float2 f1 = __half22float2(*reinterpret_cast<__half2*>(&v.y));
            s.x += f0.x; s.y += f0.y; s.z += f1.x; s.w += f1.y;
        }
    }
    float sc = 1.f / fmaxf((float)(end - beg), 1.f);
    uint2 o;
    __half2 h0 = __floats2half2_rn(s.x * sc, s.y * sc);
    __half2 h1 = __floats2half2_rn(s.z * sc, s.w * sc);
    o.x = *reinterpret_cast<unsigned*>(&h0);
    o.y = *reinterpret_cast<unsigned*>(&h1);
    ((uint2*)(seg + (size_t)w * D_IN))[lane] = o;
}

// ---------------- fused reduce 2 + final ----------------
// out[d] = Ys[d] + b2 + sum_r (1/deg_r) * sum_{e in (r,d)} Yh[src_e, r*128..]
__global__ void reduce2_final_kernel(const __half* __restrict__ Yh, const float* __restrict__ Ys,
                                     const int* __restrict__ offs, const int* __restrict__ elist,
                                     const float* __restrict__ bs, float* __restrict__ out) {
    int d = (blockIdx.x * blockDim.x + threadIdx.x) >> 5;
    int lane = threadIdx.x & 31;
    if (d >= NODES) return;

    float4 acc = __ldg(((const float4*)(Ys + (size_t)d * D_OUT)) + lane);
    float4 bv  = __ldg(((const float4*)bs) + lane);
    acc.x += bv.x; acc.y += bv.y; acc.z += bv.z; acc.w += bv.w;

#pragma unroll
    for (int r = 0; r < RELS; r++) {
        int w = r * NODES + d;
        int beg = offs[w], end = offs[w + 1];
        if (beg == end) continue;
        float4 s = make_float4(0.f, 0.f, 0.f, 0.f);
        for (int i = beg; i < end; i += 32) {
            int nid = (i + lane < end) ? elist[i + lane] : 0;
            int cnt = min(32, end - i);
            for (int j = 0; j < cnt; j++) {
                int sid = __shfl_sync(0xffffffffu, nid, j);
                uint2 v = __ldg(((const uint2*)(Yh + (size_t)sid * (3 * D_OUT) + r * D_OUT)) + lane);
                float2 f0 = __half22float2(*reinterpret_cast<__half2*>(&v.x));
                float2 f1 = __half22float2(*reinterpret_cast<__half2*>(&v.y));
                s.x += f0.x; s.y += f0.y; s.z += f1.x; s.w += f1.y;
            }
        }
        float sc = 1.f / (float)(end - beg);
        acc.x += s.x * sc; acc.y += s.y * sc; acc.z += s.z * sc; acc.w += s.w * sc;
    }
    ((float4*)(out + (size_t)d * D_OUT))[lane] = acc;
}

// ---------------- fp16 HMMA GEMM: cp.async 3-stage, BK=64, fused concat-A ----------------
// A: [M,K] fp16 (virtual concat over chunks of width D); B: [N,K] fp16 (pre-transposed).
// C = act(A @ B^T + bias). Cols < halfCols -> Ch fp16 (stride halfCols); rest -> Cf fp32.
#define BK 64
#define TSTRIDE 72                       // halfs; bank-conflict-free (36 words/row, 4r+c distinct)
#define TILE_H (128 * TSTRIDE)           // halfs per tile (A or B)
#define NSTAGE 3
#define GEMM_SMEM (NSTAGE * 2 * TILE_H * 2)   // bytes = 110592

template <int D>
__global__ __launch_bounds__(256, 2)
void gemm_f16_kernel(const __half* __restrict__ feat, const __half* __restrict__ seg,
                     const __half* __restrict__ Bw, const float* __restrict__ bias,
                     float* __restrict__ Cf, __half* __restrict__ Ch,
                     int M, int N, int K, int halfCols, int doRelu, int doBias) {
    extern __shared__ __half smp[];
    __half* As = smp;
    __half* Bs = smp + NSTAGE * TILE_H;
    const uint32_t As_u = (uint32_t)__cvta_generic_to_shared(As);
    const uint32_t Bs_u = (uint32_t)__cvta_generic_to_shared(Bs);

    const int tid  = threadIdx.x;
    const int lane = tid & 31;
    const int warp = tid >> 5;
    const int warpM = (warp >> 2) * 64;
    const int warpN = (warp & 3) * 32;
    const int block_row = blockIdx.x * 128;
    const int block_col = blockIdx.y * 128;

    // cp.async mapping: 1024 16B-chunks per tile, 4 per thread
    const int ld_r0 = tid >> 1;          // 0..127 row
    const int ld_c0 = (tid & 1) * 32;    // 0 or 32 (halfs); +8,+16,+24 via l

    float acc[4][4][4];
#pragma unroll
    for (int i = 0; i < 4; i++)
#pragma unroll
        for (int j = 0; j < 4; j++)
#pragma unroll
            for (int c = 0; c < 4; c++) acc[i][j][c] = 0.f;

    auto load_stage = [&](int buf, int kb) {
        const int chunk = kb / D;
        const int col0 = kb - chunk * D;
        const __half* abase = (chunk == 0) ? feat : (seg + (size_t)(chunk - 1) * NODES * D);
        int gr = block_row + ld_r0;
        const __half* ag = abase + (size_t)gr * D + col0 + ld_c0;
        uint32_t sa = As_u + (uint32_t)(buf * TILE_H + ld_r0 * TSTRIDE + ld_c0) * 2u;
        int sz = (gr < M) ? 16 : 0;
#pragma unroll
        for (int l = 0; l < 4; l++) {
            asm volatile("cp.async.cg.shared.global [%0], [%1], 16, %2;"
                         :: "r"(sa + l * 16u), "l"(ag + l * 8), "r"(sz));
        }
        const __half* bg = Bw + (size_t)(block_col + ld_r0) * K + kb + ld_c0;
        uint32_t sb = Bs_u + (uint32_t)(buf * TILE_H + ld_r0 * TSTRIDE + ld_c0) * 2u;
#pragma unroll
        for (int l = 0; l < 4; l++) {
            asm volatile("cp.async.cg.shared.global [%0], [%1], 16;"
                         :: "r"(sb + l * 16u), "l"(bg + l * 8));
        }
        asm volatile("cp.async.commit_group;");
    };

    const int T = K / BK;
    load_stage(0, 0);
    load_stage(1, BK);

    for (int t = 0; t < T; t++) {
        if (t + 1 < T) {
            asm volatile("cp.async.wait_group 1;");
        } else {
            asm volatile("cp.async.wait_group 0;");
        }
        __syncthreads();
        if (t + 2 < T) load_stage((t + 2) % NSTAGE, (t + 2) * BK);

        int buf = t % NSTAGE;
        const __half* At = As + buf * TILE_H;
        const __half* Bt = Bs + buf * TILE_H;
#pragma unroll
        for (int k16 = 0; k16 < BK / 16; k16++) {
            const int k0 = k16 * 16 + (lane & 3) * 2;
            unsigned a[4][4];
#pragma unroll
            for (int mt = 0; mt < 4; mt++) {
                int row = warpM + mt * 16 + (lane >> 2);
                a[mt][0] = *(const unsigned*)(At + row * TSTRIDE + k0);
                a[mt][1] = *(const unsigned*)(At + (row + 8) * TSTRIDE + k0);
                a[mt][2] = *(const unsigned*)(At + row * TSTRIDE + k0 + 8);
                a[mt][3] = *(const unsigned*)(At + (row + 8) * TSTRIDE + k0 + 8);
            }
            unsigned b[4][2];
#pragma unroll
            for (int nt = 0; nt < 4; nt++) {
                int n = warpN + nt * 8 + (lane >> 2);
                b[nt][0] = *(const unsigned*)(Bt + n * TSTRIDE + k0);
                b[nt][1] = *(const unsigned*)(Bt + n * TSTRIDE + k0 + 8);
            }
#pragma unroll
            for (int mt = 0; mt < 4; mt++)
#pragma unroll
                for (int nt = 0; nt < 4; nt++) {
                    asm volatile(
                        "mma.sync.aligned.m16n8k16.row.col.f32.f16.f16.f32 "
                        "{%0,%1,%2,%3}, {%4,%5,%6,%7}, {%8,%9}, {%0,%1,%2,%3};"
                        : "+f"(acc[mt][nt][0]), "+f"(acc[mt][nt][1]),
                          "+f"(acc[mt][nt][2]), "+f"(acc[mt][nt][3])
                        : "r"(a[mt][0]), "r"(a[mt][1]), "r"(a[mt][2]), "r"(a[mt][3]),
                          "r"(b[nt][0]), "r"(b[nt][1]));
                }
        }
        __syncthreads();
    }

    const int fStride = N - halfCols;
#pragma unroll
    for (int mt = 0; mt < 4; mt++) {
#pragma unroll
        for (int nt = 0; nt < 4; nt++) {
            int col = block_col + warpN + nt * 8 + (lane & 3) * 2;
            float bx = doBias ? bias[col] : 0.f;
            float by = doBias ? bias[col + 1] : 0.f;
#pragma unroll
            for (int half = 0; half < 2; half++) {
                int row = block_row + warpM + mt * 16 + (lane >> 2) + half * 8;
                if (row >= M) continue;
                float vx = acc[mt][nt][half * 2 + 0] + bx;
                float vy = acc[mt][nt][half * 2 + 1] + by;
                if (doRelu) { vx = fmaxf(vx, 0.f); vy = fmaxf(vy, 0.f); }
                if (col < halfCols) {
                    *(__half2*)(Ch + (size_t)row * halfCols + col) = __floats2half2_rn(vx, vy);
                } else {
                    *(float2*)(Cf + (size_t)row * fStride + (col - halfCols)) = make_float2(vx, vy);
                }
            }
        }
    }
}

// ---------------- launch ----------------
extern "C" void kernel_launch(void* const* d_in, const int* in_sizes, int n_in,
                              void* d_out, int out_size) {
    const float* x      = (const float*)d_in[0];
    const int*   src    = (const int*)  d_in[1];
    const int*   dst    = (const int*)  d_in[2];
    const float* Wself1 = (const float*)d_in[3];
    const float* Wneigh1= (const float*)d_in[4];
    const float* b1     = (const float*)d_in[5];
    const float* Wself2 = (const float*)d_in[6];
    const float* Wneigh2= (const float*)d_in[7];
    const float* b2     = (const float*)d_in[8];
    float* out = (float*)d_out;

    float *Ys, *b1s, *b2s;
    __half *xh, *seg1, *h, *Yh, *W1h, *W2h;
    int *cnt, *offs, *bsum, *elist;
    cudaGetSymbolAddress((void**)&xh,   g_xh);
    cudaGetSymbolAddress((void**)&seg1, g_seg1);
    cudaGetSymbolAddress((void**)&h,    g_h);
    cudaGetSymbolAddress((void**)&Yh,   g_Yh);
    cudaGetSymbolAddress((void**)&Ys,   g_Ys);
    cudaGetSymbolAddress((void**)&cnt,  g_cnt);
    cudaGetSymbolAddress((void**)&offs, g_offs);
    cudaGetSymbolAddress((void**)&bsum, g_bsum);
    cudaGetSymbolAddress((void**)&elist,g_elist);
    cudaGetSymbolAddress((void**)&W1h,  g_W1h);
    cudaGetSymbolAddress((void**)&W2h,  g_W2h);
    cudaGetSymbolAddress((void**)&b1s,  g_b1s);
    cudaGetSymbolAddress((void**)&b2s,  g_b2s);

    cudaFuncSetAttribute(gemm_f16_kernel<D_IN>,
                         cudaFuncAttributeMaxDynamicSharedMemorySize, GEMM_SMEM);
    cudaFuncSetAttribute(gemm_f16_kernel<D_HID>,
                         cudaFuncAttributeMaxDynamicSharedMemorySize, GEMM_SMEM);

    // ---- zero CSR counters ----
    zero_i<<<(SCAN_N + 255) / 256, 256>>>(cnt, SCAN_N);

    // ---- weights (fp16, transposed), bias sums, x fp16 ----
    prep_w1_kernel<<<(D_HID * 4 * D_IN + 255) / 256, 256>>>(Wself1, Wneigh1, b1, W1h, b1s);
    prep_w2_kernel<<<((4 * D_OUT) * D_HID + 255) / 256, 256>>>(Wself2, Wneigh2, b2, W2h, b2s);
    prep_x_kernel<<<4096, 256>>>((const float4*)x, (__half2*)xh, (long)NODES * D_IN / 4);

    // ---- CSR build ----
    cnt_kernel<<<(RELS * EDGES + 255) / 256, 256>>>(dst, cnt);
    scan1_kernel<<<SCAN_BLOCKS, SCAN_B>>>(cnt, offs, bsum);
    scan2_kernel<<<1, SCAN_B>>>(bsum, SCAN_BLOCKS);
    scan3_kernel<<<SCAN_BLOCKS, SCAN_B>>>(offs, bsum);
    fill_kernel<<<(RELS * EDGES + 255) / 256, 256>>>(src, dst, offs, cnt, elist);

    const int reduce_blocks = (SCAN_N * 32 + 255) / 256;
    const int mblocks = (NODES + 127) / 128;

    // ---- layer 1: fp16 means -> seg1, fp16 GEMM -> h (relu+bias, fp16 out) ----
    reduce1_kernel<<<reduce_blocks, 256>>>(xh, offs, elist, seg1);
    {
        dim3 grid(mblocks, D_HID / 128);
        gemm_f16_kernel<D_IN><<<grid, 256, GEMM_SMEM>>>(xh, seg1, W1h, b1s, nullptr, h,
                                                        NODES, D_HID, 4 * D_IN,
                                                        D_HID, 1, 1);
    }

    // ---- layer 2: fp16 GEMM -> [Yh fp16 | Ys fp32], fused reduce+final -> out ----
    {
        dim3 grid(mblocks, (4 * D_OUT) / 128);
        gemm_f16_kernel<D_HID><<<grid, 256, GEMM_SMEM>>>(h, nullptr, W2h, nullptr, Ys, Yh,
                                                         NODES, 4 * D_OUT, D_HID,
                                                         3 * D_OUT, 0, 0);
    }
    reduce2_final_kernel<<<(NODES * 32 + 255) / 256, 256>>>(Yh, Ys, offs, elist, b2s, out);
}